// round 7
// baseline (speedup 1.0000x reference)
#include <cuda_runtime.h>

// Problem constants (fixed by setup_inputs)
#define BS      64
#define C_TS    128
#define C_CTS   256
#define T_LEN   2048
#define N_CAT   32
#define N_CONT  64

#define MASK_P    0.15f
#define REPLACE_P 0.80f
#define RAND_HI   0.90f   // REPLACE_P + RANDOM_P

// Decision codes (int32): -2 keep, -1 zero, >=0 swap index within row
#define CODE_KEEP  (-2)
#define CODE_ZERO  (-1)

// Scratch: per-(b,t) decision codes (512 KB each, L2-resident)
__device__ int g_code_ts [BS * T_LEN];
__device__ int g_code_cts[BS * T_LEN];

// ---------------------------------------------------------------------------
// Precompute: encode decisions for both TS tensors. Thread handles 4 t.
// ---------------------------------------------------------------------------
#define DEC_N        (BS * T_LEN)                       // 131072 per tensor
#define DEC_THREADS  256
#define DEC_PER_T    4
#define DEC_BLOCKS   ((2 * DEC_N) / (DEC_THREADS * DEC_PER_T))   // 256

__device__ __forceinline__ int decide(float um, float ua, int ridx)
{
    if (um < MASK_P) {
        if (ua < REPLACE_P) return CODE_ZERO;
        if (ua < RAND_HI)   return ridx;
    }
    return CODE_KEEP;
}

__global__ void __launch_bounds__(DEC_THREADS)
precompute_kernel(const float* __restrict__ u_ts_mask,
                  const float* __restrict__ u_ts_act,
                  const int*   __restrict__ r_ts_idx,
                  const float* __restrict__ u_cts_mask,
                  const float* __restrict__ u_cts_act,
                  const int*   __restrict__ r_cts_idx)
{
    unsigned base = (blockIdx.x * DEC_THREADS + threadIdx.x) * DEC_PER_T;
    const float* um;
    const float* ua;
    const int*   ri;
    int* code;
    unsigned off;
    if (base < DEC_N) { um = u_ts_mask;  ua = u_ts_act;  ri = r_ts_idx;  code = g_code_ts;  off = base; }
    else              { um = u_cts_mask; ua = u_cts_act; ri = r_cts_idx; code = g_code_cts; off = base - DEC_N; }

    float4 m4 = *(const float4*)(um + off);
    float4 a4 = *(const float4*)(ua + off);
    int4   r4 = *(const int4*)  (ri + off);

    int4 c4;
    c4.x = decide(m4.x, a4.x, r4.x);
    c4.y = decide(m4.y, a4.y, r4.y);
    c4.z = decide(m4.z, a4.z, r4.z);
    c4.w = decide(m4.w, a4.w, r4.w);
    *(int4*)(code + off) = c4;
}

// ---------------------------------------------------------------------------
// Fused streaming kernel: exact R1-proven body. Thread = 4 consecutive t.
// Loads: int4 code (L2-resident) + float4 x. Store: float4. 32-bit indexing.
// ---------------------------------------------------------------------------
#define MAIN_THREADS 256
#define GROUPS_PER_ROW (T_LEN / 4)                                       // 512
#define TS_BLOCKS    ((int)((long)BS * C_TS  * T_LEN / 4 / MAIN_THREADS)) // 16384
#define CTS_BLOCKS   ((int)((long)BS * C_CTS * T_LEN / 4 / MAIN_THREADS)) // 32768

__global__ void __launch_bounds__(MAIN_THREADS)
fused_mask_kernel(const float* __restrict__ x_ts,
                  float* __restrict__ out_ts,
                  const float* __restrict__ x_cts,
                  float* __restrict__ out_cts,
                  const int*   __restrict__ x_cat,
                  const float* __restrict__ x_cont,
                  const float* __restrict__ u_cat_mask,
                  const float* __restrict__ u_cat_act,
                  const int*   __restrict__ r_cat_val,
                  const float* __restrict__ u_cont_mask,
                  const float* __restrict__ u_cont_act,
                  const int*   __restrict__ r_cont_idx,
                  float* __restrict__ out_cat,
                  float* __restrict__ out_cont)
{
    unsigned blk = blockIdx.x;
    unsigned tid = threadIdx.x;

    if (blk < TS_BLOCKS + CTS_BLOCKS) {
        const float* x;
        float* out;
        const int* code;
        unsigned logC;
        if (blk < TS_BLOCKS) {
            x = x_ts; out = out_ts; code = g_code_ts; logC = 7;
        } else {
            blk -= TS_BLOCKS;
            x = x_cts; out = out_cts; code = g_code_cts; logC = 8;
        }

        unsigned gid = blk * MAIN_THREADS + tid;
        unsigned t0 = (gid & (GROUPS_PER_ROW - 1)) * 4;
        unsigned bc = gid >> 9;                   // / GROUPS_PER_ROW
        unsigned b  = bc >> logC;

        const int4 c4 = *(const int4*)(code + b * T_LEN + t0);
        const float* row = x + bc * T_LEN;
        float4 x4 = *(const float4*)(row + t0);

        float v[4] = {x4.x, x4.y, x4.z, x4.w};
        int   c[4] = {c4.x, c4.y, c4.z, c4.w};
#pragma unroll
        for (int i = 0; i < 4; i++) {
            int ci = c[i];
            if (ci != CODE_KEEP) {
                v[i] = (ci >= 0) ? __ldg(row + ci) : 0.0f;
            }
        }

        *(float4*)(out + bc * T_LEN + t0) = make_float4(v[0], v[1], v[2], v[3]);
        return;
    }

    // ---- static cat + cont (single tail block, 256 threads) ----
    __shared__ float partial[4][N_CONT];
    __shared__ float means[N_CONT];

    {
        unsigned j = tid & (N_CONT - 1);     // column
        unsigned chunk = tid >> 6;           // 0..3, 16 rows each
        float s = 0.0f;
        for (unsigned b = chunk * 16; b < chunk * 16 + 16; b++)
            s += x_cont[b * N_CONT + j];
        partial[chunk][j] = s;
    }
    __syncthreads();
    if (tid < N_CONT) {
        means[tid] = (partial[0][tid] + partial[1][tid] +
                      partial[2][tid] + partial[3][tid]) * (1.0f / BS);
    }
    __syncthreads();

    // categorical: BS*N_CAT = 2048 elements
    for (unsigned i = tid; i < BS * N_CAT; i += MAIN_THREADS) {
        float um = u_cat_mask[i];
        float ua = u_cat_act[i];
        int v = x_cat[i];
        if (um < MASK_P) {
            if (ua < REPLACE_P)    v = 0;
            else if (ua < RAND_HI) v = r_cat_val[i];
        }
        out_cat[i] = (float)v;
    }

    // continuous: BS*N_CONT = 4096 elements
    for (unsigned i = tid; i < BS * N_CONT; i += MAIN_THREADS) {
        unsigned j = i & (N_CONT - 1);
        float um = u_cont_mask[i];
        float ua = u_cont_act[i];
        float v = x_cont[i];
        if (um < MASK_P) {
            if (ua < REPLACE_P)    v = means[j];
            else if (ua < RAND_HI) v = x_cont[r_cont_idx[i] * N_CONT + j];
        }
        out_cont[i] = v;
    }
}

// ---------------------------------------------------------------------------
// Launch
// ---------------------------------------------------------------------------
extern "C" void kernel_launch(void* const* d_in, const int* in_sizes, int n_in,
                              void* d_out, int out_size)
{
    const float* x_ts     = (const float*)d_in[0];
    const float* x_ts_cat = (const float*)d_in[1];
    const int*   x_cat    = (const int*)  d_in[2];
    const float* x_cont   = (const float*)d_in[3];

    const float* u_ts_mask  = (const float*)d_in[4];
    const float* u_ts_act   = (const float*)d_in[5];
    const int*   r_ts_idx   = (const int*)  d_in[6];
    const float* u_cts_mask = (const float*)d_in[7];
    const float* u_cts_act  = (const float*)d_in[8];
    const int*   r_cts_idx  = (const int*)  d_in[9];

    const float* u_cat_mask = (const float*)d_in[10];
    const float* u_cat_act  = (const float*)d_in[11];
    const int*   r_cat_val  = (const int*)  d_in[12];
    const float* u_cont_mask= (const float*)d_in[13];
    const float* u_cont_act = (const float*)d_in[14];
    const int*   r_cont_idx = (const int*)  d_in[15];

    float* out = (float*)d_out;
    const long TS_ELEMS  = (long)BS * C_TS  * T_LEN;   // 16,777,216
    const long CTS_ELEMS = (long)BS * C_CTS * T_LEN;   // 33,554,432
    float* out_ts   = out;
    float* out_cts  = out + TS_ELEMS;
    float* out_cat  = out + TS_ELEMS + CTS_ELEMS;
    float* out_cont = out_cat + (long)BS * N_CAT;

    precompute_kernel<<<DEC_BLOCKS, DEC_THREADS>>>(
        u_ts_mask, u_ts_act, r_ts_idx,
        u_cts_mask, u_cts_act, r_cts_idx);

    fused_mask_kernel<<<TS_BLOCKS + CTS_BLOCKS + 1, MAIN_THREADS>>>(
        x_ts, out_ts, x_ts_cat, out_cts,
        x_cat, x_cont,
        u_cat_mask, u_cat_act, r_cat_val,
        u_cont_mask, u_cont_act, r_cont_idx,
        out_cat, out_cont);
}